// round 2
// baseline (speedup 1.0000x reference)
#include <cuda_runtime.h>
#include <math.h>

// ---------------------------------------------------------------------------
// InstructPerceiverResampler — Round 1 baseline (fp32 SIMT, exact math)
//
// Pipeline (all launches on the default stream, graph-capturable, no allocs):
//   xhat = rownorm(x)                              [once; nm affine folded into GEMM A-load]
//   lat[:, :64]  = latents (broadcast)
//   lat[:, 64:]  = gelu(text @ w1 + b1) @ w2 + b2  [GEMM epilogues + row remap]
//   6x layer:
//     lhat = rownorm(lat)
//     q    = (lhat*nl_w+nl_b) @ Wq
//     kv[x rows]   = (xhat*nm_w+nm_b) @ Wkv        [row remap b*857 + j]
//     kv[lat rows] = (lhat*nl_w+nl_b) @ Wkv        [row remap b*857 + 729 + j]
//     ao   = flash_attention(q, kv)                [online softmax, smem-resident]
//     lat += ao @ Wo
//     lhat = rownorm(lat)
//     ffh  = gelu((lhat*ffln_w+ffln_b) @ ff_w1)
//     lat += ffh @ ff_w2
//   out = LN(lat[:, :64]) * out_ln_w + out_ln_b
// ---------------------------------------------------------------------------

#define DIMC     1152
#define DIM_LLM  4096
#define BATCH    32
#define NVX      729
#define NTXT     64
#define N2       128
#define NKV      857
#define HEADS    16
#define DHEAD    96
#define INNER    1536
#define FF_INNER 4608
#define DEPTH    6

#define XROWS (BATCH * NVX)   // 23328
#define LROWS (BATCH * N2)    // 4096
#define TROWS (BATCH * NTXT)  // 2048

#define ATT_SCALE 0.10206207261596577f  // 96^-0.5

// ---------------- scratch (device globals; no runtime allocation) ----------
__device__ float g_xhat[XROWS * DIMC];              // 107.5 MB
__device__ float g_lat [LROWS * DIMC];
__device__ float g_lhat[LROWS * DIMC];
__device__ float g_tmp1[TROWS * DIMC];
__device__ float g_q   [LROWS * INNER];
__device__ float g_kv  [(size_t)BATCH * NKV * (2 * INNER)];  // 337 MB
__device__ float g_ao  [LROWS * INNER];
__device__ float g_ffh [LROWS * FF_INNER];

__device__ __forceinline__ float gelu_exact(float v) {
    return 0.5f * v * (1.0f + erff(v * 0.7071067811865476f));
}

// ---------------------------------------------------------------------------
// Generic SGEMM: C[map(r)] (op)= epilogue(A'[M,K] @ B[K,N])
//   A'[r,k] = ATRANS ? A[r,k]*aw[k]+ab[k] : A[r,k]
//   CMAP: 0 ident | 1 txt->lat rows | 2 kv x-rows | 3 kv lat-rows  (ldC == N)
//   EPI : 0 store | 1 +bias | 2 +bias,gelu | 3 gelu | 4 C += v (residual)
// 128x128 block tile, BK=8, 256 threads, 8x8 per-thread tile, double-buffered.
// Requires: N % 128 == 0, K % 8 == 0 (true for all call sites). M ragged OK.
// ---------------------------------------------------------------------------
template <int CMAP, int EPI, bool ATRANS>
__global__ void __launch_bounds__(256)
sgemm_kernel(const float* __restrict__ A, const float* __restrict__ B,
             float* __restrict__ C, int M, int N, int K,
             const float* __restrict__ aw, const float* __restrict__ ab,
             const float* __restrict__ bias)
{
    __shared__ float As[2][8][128];
    __shared__ float Bs[2][8][128];

    const int tid  = threadIdx.x;
    const int tx   = tid & 15;        // col group 0..15
    const int ty   = tid >> 4;        // row group 0..15
    const int m0   = blockIdx.y * 128;
    const int n0   = blockIdx.x * 128;

    const int arow  = tid >> 1;       // 0..127 (tile row for A load)
    const int akoff = (tid & 1) * 4;  // 0 or 4
    const int brow  = tid >> 5;       // 0..7  (tile row for B load)
    const int bcol  = (tid & 31) * 4; // 0..124

    float acc[8][8];
    #pragma unroll
    for (int i = 0; i < 8; i++)
        #pragma unroll
        for (int j = 0; j < 8; j++) acc[i][j] = 0.f;

    const int nk = K >> 3;

    float4 aReg, bReg;
    // --- prefetch tile 0 ---
    {
        const int r = m0 + arow;
        if (r < M) aReg = *(const float4*)(A + (size_t)r * K + akoff);
        else       aReg = make_float4(0.f, 0.f, 0.f, 0.f);
        if (ATRANS) {
            aReg.x = aReg.x * aw[akoff + 0] + ab[akoff + 0];
            aReg.y = aReg.y * aw[akoff + 1] + ab[akoff + 1];
            aReg.z = aReg.z * aw[akoff + 2] + ab[akoff + 2];
            aReg.w = aReg.w * aw[akoff + 3] + ab[akoff + 3];
        }
        bReg = *(const float4*)(B + (size_t)brow * N + n0 + bcol);
    }
    As[0][akoff + 0][arow] = aReg.x;
    As[0][akoff + 1][arow] = aReg.y;
    As[0][akoff + 2][arow] = aReg.z;
    As[0][akoff + 3][arow] = aReg.w;
    *(float4*)&Bs[0][brow][bcol] = bReg;
    __syncthreads();

    int cur = 0;
    for (int kt = 0; kt < nk; kt++) {
        if (kt + 1 < nk) {
            const int k0 = (kt + 1) * 8;
            const int r  = m0 + arow;
            if (r < M) aReg = *(const float4*)(A + (size_t)r * K + k0 + akoff);
            else       aReg = make_float4(0.f, 0.f, 0.f, 0.f);
            if (ATRANS) {
                aReg.x = aReg.x * aw[k0 + akoff + 0] + ab[k0 + akoff + 0];
                aReg.y = aReg.y * aw[k0 + akoff + 1] + ab[k0 + akoff + 1];
                aReg.z = aReg.z * aw[k0 + akoff + 2] + ab[k0 + akoff + 2];
                aReg.w = aReg.w * aw[k0 + akoff + 3] + ab[k0 + akoff + 3];
            }
            bReg = *(const float4*)(B + (size_t)(k0 + brow) * N + n0 + bcol);
        }
        #pragma unroll
        for (int kk = 0; kk < 8; kk++) {
            float a[8], b[8];
            *(float4*)&a[0] = *(const float4*)&As[cur][kk][ty * 8];
            *(float4*)&a[4] = *(const float4*)&As[cur][kk][ty * 8 + 4];
            *(float4*)&b[0] = *(const float4*)&Bs[cur][kk][tx * 8];
            *(float4*)&b[4] = *(const float4*)&Bs[cur][kk][tx * 8 + 4];
            #pragma unroll
            for (int i = 0; i < 8; i++)
                #pragma unroll
                for (int j = 0; j < 8; j++)
                    acc[i][j] += a[i] * b[j];
        }
        if (kt + 1 < nk) {
            const int nb = cur ^ 1;
            As[nb][akoff + 0][arow] = aReg.x;
            As[nb][akoff + 1][arow] = aReg.y;
            As[nb][akoff + 2][arow] = aReg.z;
            As[nb][akoff + 3][arow] = aReg.w;
            *(float4*)&Bs[nb][brow][bcol] = bReg;
            __syncthreads();
            cur = nb;
        }
    }

    // --- epilogue ---
    #pragma unroll
    for (int i = 0; i < 8; i++) {
        const int gr = m0 + ty * 8 + i;
        if (gr >= M) continue;
        size_t crow;
        if      (CMAP == 0) crow = (size_t)gr;
        else if (CMAP == 1) crow = (size_t)(gr >> 6) * 128 + 64 + (gr & 63);
        else if (CMAP == 2) crow = (size_t)(gr / NVX) * NKV + (gr % NVX);
        else                crow = (size_t)(gr >> 7) * NKV + NVX + (gr & 127);
        float* cp = C + crow * N + n0 + tx * 8;
        #pragma unroll
        for (int j = 0; j < 8; j++) {
            float v = acc[i][j];
            if (EPI == 1 || EPI == 2) v += bias[n0 + tx * 8 + j];
            if (EPI == 2 || EPI == 3) v = gelu_exact(v);
            if (EPI == 4) cp[j] += v;
            else          cp[j] = v;
        }
    }
}

// ---------------------------------------------------------------------------
// Row LayerNorm (no affine): out[r,:] = (x - mu) * rsqrt(var + 1e-5)
// one block / row, 256 threads
// ---------------------------------------------------------------------------
__global__ void ln_rows(const float* __restrict__ in, float* __restrict__ out,
                        int ncols)
{
    const int row = blockIdx.x;
    const float* xp = in + (size_t)row * ncols;
    float* yp = out + (size_t)row * ncols;
    __shared__ float buf[40];
    const int tid = threadIdx.x, lane = tid & 31, wid = tid >> 5;

    float s = 0.f;
    for (int c = tid; c < ncols; c += 256) s += xp[c];
    #pragma unroll
    for (int o = 16; o > 0; o >>= 1) s += __shfl_xor_sync(0xffffffffu, s, o);
    if (lane == 0) buf[wid] = s;
    __syncthreads();
    if (tid == 0) {
        float t = 0.f;
        for (int w = 0; w < 8; w++) t += buf[w];
        buf[32] = t / (float)ncols;
    }
    __syncthreads();
    const float mu = buf[32];

    float v = 0.f;
    for (int c = tid; c < ncols; c += 256) { float d = xp[c] - mu; v += d * d; }
    #pragma unroll
    for (int o = 16; o > 0; o >>= 1) v += __shfl_xor_sync(0xffffffffu, v, o);
    if (lane == 0) buf[wid] = v;
    __syncthreads();
    if (tid == 0) {
        float t = 0.f;
        for (int w = 0; w < 8; w++) t += buf[w];
        buf[33] = rsqrtf(t / (float)ncols + 1e-5f);
    }
    __syncthreads();
    const float rstd = buf[33];

    for (int c = tid; c < ncols; c += 256) yp[c] = (xp[c] - mu) * rstd;
}

// Final LN with affine + latent-row gather: out[b*64+i] <- lat[b*128+i]
__global__ void ln_out_kernel(const float* __restrict__ lat,
                              const float* __restrict__ w,
                              const float* __restrict__ b,
                              float* __restrict__ out)
{
    const int r = blockIdx.x;  // 0..2047
    const int src = (r >> 6) * 128 + (r & 63);
    const float* xp = lat + (size_t)src * DIMC;
    float* yp = out + (size_t)r * DIMC;
    __shared__ float buf[40];
    const int tid = threadIdx.x, lane = tid & 31, wid = tid >> 5;

    float s = 0.f;
    for (int c = tid; c < DIMC; c += 256) s += xp[c];
    #pragma unroll
    for (int o = 16; o > 0; o >>= 1) s += __shfl_xor_sync(0xffffffffu, s, o);
    if (lane == 0) buf[wid] = s;
    __syncthreads();
    if (tid == 0) {
        float t = 0.f;
        for (int wj = 0; wj < 8; wj++) t += buf[wj];
        buf[32] = t / (float)DIMC;
    }
    __syncthreads();
    const float mu = buf[32];

    float v = 0.f;
    for (int c = tid; c < DIMC; c += 256) { float d = xp[c] - mu; v += d * d; }
    #pragma unroll
    for (int o = 16; o > 0; o >>= 1) v += __shfl_xor_sync(0xffffffffu, v, o);
    if (lane == 0) buf[wid] = v;
    __syncthreads();
    if (tid == 0) {
        float t = 0.f;
        for (int wj = 0; wj < 8; wj++) t += buf[wj];
        buf[33] = rsqrtf(t / (float)DIMC + 1e-5f);
    }
    __syncthreads();
    const float rstd = buf[33];

    for (int c = tid; c < DIMC; c += 256)
        yp[c] = (xp[c] - mu) * rstd * w[c] + b[c];
}

// lat[b*128+i, :] = latents[i, :]   for i in [0,64)
__global__ void bcast_latents(const float* __restrict__ latents,
                              float* __restrict__ lat)
{
    const int r = blockIdx.x;  // 0..2047 = b*64+i
    const int b = r >> 6, i = r & 63;
    const float* sp = latents + (size_t)i * DIMC;
    float* dp = lat + ((size_t)b * 128 + i) * DIMC;
    for (int c = threadIdx.x; c < DIMC; c += 128) dp[c] = sp[c];
}

// ---------------------------------------------------------------------------
// Flash attention: grid (4 qtiles, 16 heads, 32 batch), 256 threads.
// Per block: 32 queries x 96 dims; online softmax over 857 keys in chunks of 32.
// Thread t: query qi = t>>3, covers dims [12*(t&7), 12*(t&7)+12).
// ---------------------------------------------------------------------------
__global__ void __launch_bounds__(256)
attn_kernel(const float* __restrict__ q, const float* __restrict__ kv,
            float* __restrict__ o)
{
    __shared__ float qs[32][100];
    __shared__ float ks[32][100];
    __shared__ float vs[32][100];
    __shared__ float ps[32][33];

    const int qt = blockIdx.x, h = blockIdx.y, b = blockIdx.z;
    const int tid = threadIdx.x;
    const int qi = tid >> 3, l8 = tid & 7, d0 = l8 * 12;

    for (int idx = tid; idx < 32 * 96; idx += 256) {
        const int r = idx / 96, d = idx % 96;
        qs[r][d] = q[(size_t)(b * 128 + qt * 32 + r) * INNER + h * 96 + d] * ATT_SCALE;
    }

    float m = -1e30f, l = 0.f;
    float acc[12];
    #pragma unroll
    for (int d = 0; d < 12; d++) acc[d] = 0.f;

    for (int j0 = 0; j0 < NKV; j0 += 32) {
        __syncthreads();  // protects qs (first iter) and ks/vs/ps reuse
        for (int idx = tid; idx < 32 * 96; idx += 256) {
            const int r = idx / 96, d = idx % 96;
            const int jj = j0 + r;
            float kval = 0.f, vval = 0.f;
            if (jj < NKV) {
                const size_t base = (size_t)(b * NKV + jj) * 3072 + h * 96 + d;
                kval = kv[base];
                vval = kv[base + INNER];
            }
            ks[r][d] = kval;
            vs[r][d] = vval;
        }
        __syncthreads();

        float s[4];
        float mc = -1e30f;
        #pragma unroll
        for (int kk = 0; kk < 4; kk++) {
            const int j = l8 + 8 * kk;
            float a = 0.f;
            #pragma unroll 8
            for (int d = 0; d < 96; d++) a += qs[qi][d] * ks[j][d];
            if (j0 + j >= NKV) a = -1e30f;
            s[kk] = a;
            mc = fmaxf(mc, a);
        }
        #pragma unroll
        for (int off = 4; off > 0; off >>= 1)
            mc = fmaxf(mc, __shfl_xor_sync(0xffffffffu, mc, off));
        const float mnew = fmaxf(m, mc);
        const float alpha = expf(m - mnew);
        float psum = 0.f;
        #pragma unroll
        for (int kk = 0; kk < 4; kk++) {
            const float p = expf(s[kk] - mnew);
            ps[qi][l8 + 8 * kk] = p;
            psum += p;
        }
        #pragma unroll
        for (int off = 4; off > 0; off >>= 1)
            psum += __shfl_xor_sync(0xffffffffu, psum, off);
        l = l * alpha + psum;
        m = mnew;
        __syncwarp();  // ps visibility within each 8-lane query group

        #pragma unroll
        for (int d = 0; d < 12; d++) acc[d] *= alpha;
        for (int j = 0; j < 32; j++) {
            const float p = ps[qi][j];
            #pragma unroll
            for (int d = 0; d < 12; d++) acc[d] += p * vs[j][d0 + d];
        }
    }

    const float inv = 1.f / l;
    float* op = o + (size_t)(b * 128 + qt * 32 + qi) * INNER + h * 96 + d0;
    #pragma unroll
    for (int d = 0; d < 12; d++) op[d] = acc[d] * inv;
}

// ---------------------------------------------------------------------------
extern "C" void kernel_launch(void* const* d_in, const int* in_sizes, int n_in,
                              void* d_out, int out_size)
{
    const float* x       = (const float*)d_in[0];
    const float* temb    = (const float*)d_in[1];
    const float* latents = (const float*)d_in[2];
    const float* txt_w1  = (const float*)d_in[3];
    const float* txt_b1  = (const float*)d_in[4];
    const float* txt_w2  = (const float*)d_in[5];
    const float* txt_b2  = (const float*)d_in[6];
    const float* nm_w    = (const float*)d_in[7];
    const float* nm_b    = (const float*)d_in[8];
    const float* nl_w    = (const float*)d_in[9];
    const float* nl_b    = (const float*)d_in[10];
    const float* Wq      = (const float*)d_in[11];
    const float* Wkv     = (const float*)d_in[12];
    const float* Wo      = (const float*)d_in[13];
    const float* ffln_w  = (const float*)d_in[14];
    const float* ffln_b  = (const float*)d_in[15];
    const float* ff_w1   = (const float*)d_in[16];
    const float* ff_w2   = (const float*)d_in[17];
    const float* oln_w   = (const float*)d_in[18];
    const float* oln_b   = (const float*)d_in[19];
    float* out = (float*)d_out;

    float *xhat, *lat, *lhat, *tmp1, *qb, *kvb, *ao, *ffh;
    cudaGetSymbolAddress((void**)&xhat, g_xhat);
    cudaGetSymbolAddress((void**)&lat,  g_lat);
    cudaGetSymbolAddress((void**)&lhat, g_lhat);
    cudaGetSymbolAddress((void**)&tmp1, g_tmp1);
    cudaGetSymbolAddress((void**)&qb,   g_q);
    cudaGetSymbolAddress((void**)&kvb,  g_kv);
    cudaGetSymbolAddress((void**)&ao,   g_ao);
    cudaGetSymbolAddress((void**)&ffh,  g_ffh);

    // xhat = rownorm(x) once (layer affine folded into GEMM A-loads)
    ln_rows<<<XROWS, 256>>>(x, xhat, DIMC);

    // lat[:, :64] = latents
    bcast_latents<<<TROWS, 128>>>(latents, lat);

    // txt: tmp1 = gelu(temb @ w1 + b1) ; lat[:, 64:] = tmp1 @ w2 + b2
    sgemm_kernel<0, 2, false><<<dim3(DIMC / 128, TROWS / 128), 256>>>(
        temb, txt_w1, tmp1, TROWS, DIMC, DIM_LLM, nullptr, nullptr, txt_b1);
    sgemm_kernel<1, 1, false><<<dim3(DIMC / 128, TROWS / 128), 256>>>(
        tmp1, txt_w2, lat, TROWS, DIMC, DIMC, nullptr, nullptr, txt_b2);

    for (int i = 0; i < DEPTH; i++) {
        const float* nw = nl_w + (size_t)i * DIMC;
        const float* nb = nl_b + (size_t)i * DIMC;
        const float* mw = nm_w + (size_t)i * DIMC;
        const float* mb = nm_b + (size_t)i * DIMC;

        ln_rows<<<LROWS, 256>>>(lat, lhat, DIMC);

        // q = (lhat*nl + nlb) @ Wq[i]
        sgemm_kernel<0, 0, true><<<dim3(INNER / 128, LROWS / 128), 256>>>(
            lhat, Wq + (size_t)i * DIMC * INNER, qb, LROWS, INNER, DIMC,
            nw, nb, nullptr);

        // kv x-rows
        sgemm_kernel<2, 0, true><<<dim3(3072 / 128, (XROWS + 127) / 128), 256>>>(
            xhat, Wkv + (size_t)i * DIMC * 3072, kvb, XROWS, 3072, DIMC,
            mw, mb, nullptr);
        // kv lat-rows
        sgemm_kernel<3, 0, true><<<dim3(3072 / 128, LROWS / 128), 256>>>(
            lhat, Wkv + (size_t)i * DIMC * 3072, kvb, LROWS, 3072, DIMC,
            nw, nb, nullptr);

        attn_kernel<<<dim3(4, HEADS, BATCH), 256>>>(qb, kvb, ao);

        // lat += ao @ Wo[i]
        sgemm_kernel<0, 4, false><<<dim3(DIMC / 128, LROWS / 128), 256>>>(
            ao, Wo + (size_t)i * INNER * DIMC, lat, LROWS, DIMC, INNER,
            nullptr, nullptr, nullptr);

        ln_rows<<<LROWS, 256>>>(lat, lhat, DIMC);

        // ffh = gelu((lhat*ffln + fflnb) @ ff_w1[i])
        sgemm_kernel<0, 3, true><<<dim3(FF_INNER / 128, LROWS / 128), 256>>>(
            lhat, ff_w1 + (size_t)i * DIMC * FF_INNER, ffh, LROWS, FF_INNER, DIMC,
            ffln_w + (size_t)i * DIMC, ffln_b + (size_t)i * DIMC, nullptr);

        // lat += ffh @ ff_w2[i]
        sgemm_kernel<0, 4, false><<<dim3(DIMC / 128, LROWS / 128), 256>>>(
            ffh, ff_w2 + (size_t)i * FF_INNER * DIMC, lat, LROWS, DIMC, FF_INNER,
            nullptr, nullptr, nullptr);
    }

    ln_out_kernel<<<TROWS, 256>>>(lat, oln_w, oln_b, out);
}